// round 13
// baseline (speedup 1.0000x reference)
#include <cuda_runtime.h>

// Problem constants
#define BB   64
#define NN   8192
#define DIN  64
#define DOUT 64
#define DD   10
#define CC   4
#define NPC  2048

#define K1_CHUNKS 64
#define K1_NODES  (NN / K1_CHUNKS)   // 128

#define NT 4    // nodes per block in k3
#define BT 32   // batch tile (2 iterations)
#define ZPAD 36 // padded bb-row stride for sZ (floats)

typedef unsigned long long u64;

__device__ __forceinline__ u64 pk2(float lo, float hi) {
    u64 r; asm("mov.b64 %0,{%1,%2};" : "=l"(r) : "f"(lo), "f"(hi)); return r;
}
__device__ __forceinline__ u64 dup2(float v) { return pk2(v, v); }
__device__ __forceinline__ void f2fma(u64& d, u64 a, u64 b) {
    asm("fma.rn.f32x2 %0,%1,%2,%3;" : "=l"(d) : "l"(a), "l"(b), "l"(d));
}
__device__ __forceinline__ u64 f2mul(u64 a, u64 b) {
    u64 r; asm("mul.rn.f32x2 %0,%1,%2;" : "=l"(r) : "l"(a), "l"(b)); return r;
}
__device__ __forceinline__ float2 u2f(u64 v) {
    float2 f; asm("mov.b64 {%0,%1},%2;" : "=f"(f.x), "=f"(f.y) : "l"(v)); return f;
}

// Scratch
__device__ float g_part[BB * K1_CHUNKS * DD * DIN];
__device__ float g_sumEH[BB * DD * DIN];

// ---------------------------------------------------------------------------
// Kernel 1: partial sum_EH. Warp covers Din (32 lanes x float2), acc[DD] u64.
// K1_CHUNKS=64 -> 4096 CTAs for more parallelism / shorter waves.
// ---------------------------------------------------------------------------
__global__ __launch_bounds__(256, 4) void k1_partial(
    const float* __restrict__ x, const float* __restrict__ emb,
    const float* __restrict__ mask, const int* __restrict__ nodes_per)
{
    __shared__ u64   s_tE[K1_NODES * DD];   // 10 KB
    __shared__ int   s_g[K1_NODES];
    __shared__ float s_red[8][DD * DIN];    // 20 KB

    const int t = threadIdx.x;
    const int b = blockIdx.y, chunk = blockIdx.x;
    const int p0 = chunk * K1_NODES;

    if (t < K1_NODES) s_g[t] = nodes_per[p0 + t];
    __syncthreads();
    for (int e = t; e < K1_NODES * DD; e += 256) {
        int p = e / DD, d = e - p * DD;
        s_tE[e] = dup2(fmaxf(emb[(size_t)s_g[p] * DD + d], 0.f));
    }
    __syncthreads();

    const int w = t >> 5, lane = t & 31;
    u64 acc[DD];
#pragma unroll
    for (int d = 0; d < DD; d++) acc[d] = 0ull;

    const float* xb = x + (size_t)b * NN * DIN + lane * 2;
    const float* mb = mask + (size_t)b * NN;
    const int base = w * (K1_NODES / 8);   // 16 nodes per warp

#pragma unroll 1
    for (int j = 0; j < K1_NODES / 8; j += 4) {
        int g4[4]; float m4[4]; float2 x4[4];
#pragma unroll
        for (int q = 0; q < 4; q++) g4[q] = s_g[base + j + q];
#pragma unroll
        for (int q = 0; q < 4; q++) {
            m4[q] = __ldg(&mb[g4[q]]);
            x4[q] = *(const float2*)(xb + (size_t)g4[q] * DIN);
        }
#pragma unroll
        for (int q = 0; q < 4; q++) {
            u64 z = f2mul(pk2(x4[q].x, x4[q].y), dup2(m4[q]));
            const u64* te = &s_tE[(base + j + q) * DD];
#pragma unroll
            for (int dp = 0; dp < DD / 2; dp++) {
                ulonglong2 tv = *(const ulonglong2*)(te + dp * 2);
                f2fma(acc[dp * 2],     tv.x, z);
                f2fma(acc[dp * 2 + 1], tv.y, z);
            }
        }
    }
#pragma unroll
    for (int d = 0; d < DD; d++)
        *(float2*)&s_red[w][d * DIN + lane * 2] = u2f(acc[d]);
    __syncthreads();
    for (int di = t; di < DD * DIN; di += 256) {
        float s = 0.f;
#pragma unroll
        for (int w2 = 0; w2 < 8; w2++) s += s_red[w2][di];
        g_part[((size_t)b * K1_CHUNKS + chunk) * (DD * DIN) + di] = s;
    }
}

__global__ __launch_bounds__(256) void k2_reduce()
{
    int idx = blockIdx.x * 256 + threadIdx.x;
    if (idx >= BB * DD * DIN) return;
    int b = idx / (DD * DIN), di = idx - b * (DD * DIN);
    float s = 0.f;
#pragma unroll
    for (int k = 0; k < K1_CHUNKS; k++)
        s += g_part[((size_t)b * K1_CHUNKS + k) * (DD * DIN) + di];
    g_sumEH[idx] = s;
}

// ---------------------------------------------------------------------------
// Kernel 3: R9 design (scalar Z in [nt][k][bb], 2 CTAs/SM) but 512 threads
// -> 32 warps/SM = 8/SMSP for latency hiding. Thread GEMM tile 2bb x 8o.
// ---------------------------------------------------------------------------
struct Smem3 {
    float sW[NT * DIN * DOUT];      // 65536 B  [nt][k][o]
    float sZ[NT * DIN * ZPAD];      // 36864 B  [nt][k][bb(32) pad 36]
    u64   stE[NT * DD];
    float sE[NT * DD];
    float sbb[NT * DOUT];
    int   sIdx[NT];
};                                   // ~104 KB -> 2 CTAs/SM

__global__ __launch_bounds__(512, 2) void k3_main(
    const float* __restrict__ x, const float* __restrict__ emb,
    const float* __restrict__ mask, const float* __restrict__ wpool,
    const float* __restrict__ bpool, const int* __restrict__ nodes_per,
    float* __restrict__ out)
{
    extern __shared__ __align__(16) char smem_raw[];
    Smem3& S = *reinterpret_cast<Smem3*>(smem_raw);

    const int t = threadIdx.x;
    const int node0 = blockIdx.x * NT;
    const int c = node0 / NPC;

    if (t < NT) S.sIdx[t] = nodes_per[node0 + t];
    __syncthreads();
    if (t < NT * DD) {
        int nt = t / DD, d = t - nt * DD;
        float v = emb[(size_t)S.sIdx[nt] * DD + d];
        S.sE[t] = v;
        S.stE[t] = dup2(fmaxf(v, 0.f));
    }
    __syncthreads();

    // bias: first 256 threads cover NT*DOUT = 256
    if (t < NT * DOUT) {
        int nt = t >> 6, o = t & 63;
        float s = 0.f;
#pragma unroll
        for (int d = 0; d < DD; d++)
            s = fmaf(S.sE[nt * DD + d], bpool[((size_t)c * DD + d) * DOUT + o], s);
        S.sbb[t] = s;
    }

    // W generation (packed): thread owns 4 consecutive floats per pg (2 pgs).
    const float* wpc = wpool + (size_t)c * DD * DIN * DOUT;
#pragma unroll
    for (int pg = 0; pg < 2; pg++) {
        u64 acc[2][NT];
#pragma unroll
        for (int h = 0; h < 2; h++)
#pragma unroll
            for (int nt = 0; nt < NT; nt++) acc[h][nt] = 0ull;
#pragma unroll
        for (int d = 0; d < DD; d++) {
            ulonglong2 wp = *(const ulonglong2*)&wpc[(size_t)d * (DIN * DOUT) + pg * 2048 + t * 4];
#pragma unroll
            for (int nt = 0; nt < NT; nt++) {
                u64 ed = dup2(S.sE[nt * DD + d]);
                f2fma(acc[0][nt], wp.x, ed);
                f2fma(acc[1][nt], wp.y, ed);
            }
        }
#pragma unroll
        for (int nt = 0; nt < NT; nt++) {
            *(float2*)&S.sW[nt * (DIN * DOUT) + pg * 2048 + t * 4]     = u2f(acc[0][nt]);
            *(float2*)&S.sW[nt * (DIN * DOUT) + pg * 2048 + t * 4 + 2] = u2f(acc[1][nt]);
        }
    }
    __syncthreads();

    // ---- Z-gen mapping: 32 i-pairs x 16 bb-pairs ----
    const int i2  = (t & 31) * 2;
    const int bbq = (t >> 5) * 2;

    // ---- GEMM mapping: 4 nodes x (8 o-groups x 16 bb-pairs) ----
    const int ntg = t >> 7;
    const int tid128 = t & 127;
    const int o0  = (tid128 & 7) * 8;
    const int bb0 = (tid128 >> 3) * 2;

    for (int bt = 0; bt < BB / BT; bt++) {
        const int b0 = bt * BT;

        // ---- Z-gen: j (batch) outer; sumEH loaded once per batch ----
        float2 zres[NT][2];
#pragma unroll
        for (int j = 0; j < 2; j++) {
            const int b = b0 + bbq + j;
            u64 sv[DD];
            const float* se = &g_sumEH[(size_t)b * (DD * DIN) + i2];
#pragma unroll
            for (int d = 0; d < DD; d++) sv[d] = *(const u64*)(se + d * DIN);
            float m4[NT]; float2 xv4[NT];
#pragma unroll
            for (int nt = 0; nt < NT; nt++) {
                int g = S.sIdx[nt];
                m4[nt]  = __ldg(&mask[(size_t)b * NN + g]);
                xv4[nt] = *(const float2*)(x + ((size_t)b * NN + g) * DIN + i2);
            }
#pragma unroll
            for (int nt = 0; nt < NT; nt++) {
                u64 z = pk2(xv4[nt].x * m4[nt], xv4[nt].y * m4[nt]);
#pragma unroll
                for (int d = 0; d < DD; d++)
                    f2fma(z, S.stE[nt * DD + d], sv[d]);
                zres[nt][j] = u2f(z);
            }
        }
#pragma unroll
        for (int nt = 0; nt < NT; nt++) {
            *(float2*)&S.sZ[(nt * DIN + i2)     * ZPAD + bbq] =
                make_float2(zres[nt][0].x, zres[nt][1].x);
            *(float2*)&S.sZ[(nt * DIN + i2 + 1) * ZPAD + bbq] =
                make_float2(zres[nt][0].y, zres[nt][1].y);
        }
        __syncthreads();

        // ---- GEMM: 2bb x 8o per thread ----
        u64 acc[2][4];
        {
            ulonglong2 bv0 = *(const ulonglong2*)&S.sbb[ntg * DOUT + o0];
            ulonglong2 bv1 = *(const ulonglong2*)&S.sbb[ntg * DOUT + o0 + 4];
            acc[0][0] = bv0.x; acc[0][1] = bv0.y; acc[0][2] = bv1.x; acc[0][3] = bv1.y;
            acc[1][0] = bv0.x; acc[1][1] = bv0.y; acc[1][2] = bv1.x; acc[1][3] = bv1.y;
        }
        const float* zbase = &S.sZ[ntg * DIN * ZPAD + bb0];
        const float* wbase = &S.sW[ntg * (DIN * DOUT) + o0];
#pragma unroll 8
        for (int k = 0; k < DIN; k++) {
            float2 zv = *(const float2*)(zbase + k * ZPAD);
            ulonglong2 w0 = *(const ulonglong2*)(wbase + (size_t)k * DOUT);
            ulonglong2 w1 = *(const ulonglong2*)(wbase + (size_t)k * DOUT + 4);
            u64 z0 = dup2(zv.x), z1 = dup2(zv.y);
            f2fma(acc[0][0], z0, w0.x); f2fma(acc[0][1], z0, w0.y);
            f2fma(acc[0][2], z0, w1.x); f2fma(acc[0][3], z0, w1.y);
            f2fma(acc[1][0], z1, w0.x); f2fma(acc[1][1], z1, w0.y);
            f2fma(acc[1][2], z1, w1.x); f2fma(acc[1][3], z1, w1.y);
        }
#pragma unroll
        for (int j = 0; j < 2; j++) {
            int b = b0 + bb0 + j;
            float* row = out + ((size_t)b * NN + node0 + ntg) * DOUT + o0;
            float2 p0 = u2f(acc[j][0]), p1 = u2f(acc[j][1]);
            float2 p2 = u2f(acc[j][2]), p3 = u2f(acc[j][3]);
            *(float4*)row       = make_float4(p0.x, p0.y, p1.x, p1.y);
            *(float4*)(row + 4) = make_float4(p2.x, p2.y, p3.x, p3.y);
        }
        __syncthreads();
    }
}

// ---------------------------------------------------------------------------
extern "C" void kernel_launch(void* const* d_in, const int* in_sizes, int n_in,
                              void* d_out, int out_size)
{
    const float* x     = (const float*)d_in[0];
    const float* emb   = (const float*)d_in[1];
    const float* mask  = (const float*)d_in[3];
    const float* wpool = (const float*)d_in[4];
    const float* bpool = (const float*)d_in[5];
    const int*   nodes = (const int*)d_in[6];
    float* out = (float*)d_out;

    cudaFuncSetAttribute(k3_main, cudaFuncAttributeMaxDynamicSharedMemorySize,
                         (int)sizeof(Smem3));

    dim3 g1(K1_CHUNKS, BB);
    k1_partial<<<g1, 256>>>(x, emb, mask, nodes);

    int tot = BB * DD * DIN;
    k2_reduce<<<(tot + 255) / 256, 256>>>();

    k3_main<<<NN / NT, 512, sizeof(Smem3)>>>(x, emb, mask, wpool, bpool, nodes, out);
}

// round 14
// speedup vs baseline: 1.0613x; 1.0613x over previous
#include <cuda_runtime.h>

// Problem constants
#define BB   64
#define NN   8192
#define DIN  64
#define DOUT 64
#define DD   10
#define CC   4
#define NPC  2048

#define K1_CHUNKS 64
#define K1_NODES  (NN / K1_CHUNKS)   // 128

#define NT 4    // nodes per block in k3
#define BT 16   // batch tile (4 iterations, double-buffered)
#define ZP 20   // padded bb-row stride for sZ (floats): 2-way conflicts

typedef unsigned long long u64;

__device__ __forceinline__ u64 pk2(float lo, float hi) {
    u64 r; asm("mov.b64 %0,{%1,%2};" : "=l"(r) : "f"(lo), "f"(hi)); return r;
}
__device__ __forceinline__ u64 dup2(float v) { return pk2(v, v); }
__device__ __forceinline__ void f2fma(u64& d, u64 a, u64 b) {
    asm("fma.rn.f32x2 %0,%1,%2,%3;" : "=l"(d) : "l"(a), "l"(b), "l"(d));
}
__device__ __forceinline__ u64 f2mul(u64 a, u64 b) {
    u64 r; asm("mul.rn.f32x2 %0,%1,%2;" : "=l"(r) : "l"(a), "l"(b)); return r;
}
__device__ __forceinline__ float2 u2f(u64 v) {
    float2 f; asm("mov.b64 {%0,%1},%2;" : "=f"(f.x), "=f"(f.y) : "l"(v)); return f;
}

// Scratch
__device__ float g_part[BB * K1_CHUNKS * DD * DIN];
__device__ float g_sumEH[BB * DD * DIN];

// ---------------------------------------------------------------------------
// Kernel 1: partial sum_EH (best measured form, ~47us). Streaming x reads.
// ---------------------------------------------------------------------------
__global__ __launch_bounds__(256, 4) void k1_partial(
    const float* __restrict__ x, const float* __restrict__ emb,
    const float* __restrict__ mask, const int* __restrict__ nodes_per)
{
    __shared__ u64   s_tE[K1_NODES * DD];
    __shared__ int   s_g[K1_NODES];
    __shared__ float s_red[8][DD * DIN];

    const int t = threadIdx.x;
    const int b = blockIdx.y, chunk = blockIdx.x;
    const int p0 = chunk * K1_NODES;

    if (t < K1_NODES) s_g[t] = nodes_per[p0 + t];
    __syncthreads();
    for (int e = t; e < K1_NODES * DD; e += 256) {
        int p = e / DD, d = e - p * DD;
        s_tE[e] = dup2(fmaxf(emb[(size_t)s_g[p] * DD + d], 0.f));
    }
    __syncthreads();

    const int w = t >> 5, lane = t & 31;
    u64 acc[DD];
#pragma unroll
    for (int d = 0; d < DD; d++) acc[d] = 0ull;

    const float* xb = x + (size_t)b * NN * DIN + lane * 2;
    const float* mb = mask + (size_t)b * NN;
    const int base = w * (K1_NODES / 8);   // 16 nodes per warp

#pragma unroll 1
    for (int j = 0; j < K1_NODES / 8; j += 4) {
        int g4[4]; float m4[4]; float2 x4[4];
#pragma unroll
        for (int q = 0; q < 4; q++) g4[q] = s_g[base + j + q];
#pragma unroll
        for (int q = 0; q < 4; q++) {
            m4[q] = __ldg(&mb[g4[q]]);
            x4[q] = __ldcs((const float2*)(xb + (size_t)g4[q] * DIN));
        }
#pragma unroll
        for (int q = 0; q < 4; q++) {
            u64 z = f2mul(pk2(x4[q].x, x4[q].y), dup2(m4[q]));
            const u64* te = &s_tE[(base + j + q) * DD];
#pragma unroll
            for (int dp = 0; dp < DD / 2; dp++) {
                ulonglong2 tv = *(const ulonglong2*)(te + dp * 2);
                f2fma(acc[dp * 2],     tv.x, z);
                f2fma(acc[dp * 2 + 1], tv.y, z);
            }
        }
    }
#pragma unroll
    for (int d = 0; d < DD; d++)
        *(float2*)&s_red[w][d * DIN + lane * 2] = u2f(acc[d]);
    __syncthreads();
    for (int di = t; di < DD * DIN; di += 256) {
        float s = 0.f;
#pragma unroll
        for (int w2 = 0; w2 < 8; w2++) s += s_red[w2][di];
        g_part[((size_t)b * K1_CHUNKS + chunk) * (DD * DIN) + di] = s;
    }
}

__global__ __launch_bounds__(256) void k2_reduce()
{
    int idx = blockIdx.x * 256 + threadIdx.x;
    if (idx >= BB * DD * DIN) return;
    int b = idx / (DD * DIN), di = idx - b * (DD * DIN);
    float s = 0.f;
#pragma unroll
    for (int k = 0; k < K1_CHUNKS; k++)
        s += g_part[((size_t)b * K1_CHUNKS + k) * (DD * DIN) + di];
    g_sumEH[idx] = s;
}

// ---------------------------------------------------------------------------
// Kernel 3: 256 thr, NT=4, BT=16, DOUBLE-BUFFERED sZ, software pipeline:
//   issue Z-loads(bt+1) -> GEMM(bt) -> compute/store Z(bt+1) -> sync
// ---------------------------------------------------------------------------
struct Smem3 {
    float sW[NT * DIN * DOUT];      // 65536 B [nt][k][o]
    float sZ[2][NT * DIN * ZP];     // 2 x 20480 B [nt][k][bb(16) pad 20]
    u64   stE[NT * DD];
    float sE[NT * DD];
    float sbb[NT * DOUT];
    int   sIdx[NT];
};                                   // ~108 KB -> 2 CTAs/SM

__global__ __launch_bounds__(256, 2) void k3_main(
    const float* __restrict__ x, const float* __restrict__ emb,
    const float* __restrict__ mask, const float* __restrict__ wpool,
    const float* __restrict__ bpool, const int* __restrict__ nodes_per,
    float* __restrict__ out)
{
    extern __shared__ __align__(16) char smem_raw[];
    Smem3& S = *reinterpret_cast<Smem3*>(smem_raw);

    const int t = threadIdx.x;
    const int node0 = blockIdx.x * NT;
    const int c = node0 / NPC;

    if (t < NT) S.sIdx[t] = nodes_per[node0 + t];
    __syncthreads();
    if (t < NT * DD) {
        int nt = t / DD, d = t - nt * DD;
        float v = emb[(size_t)S.sIdx[nt] * DD + d];
        S.sE[t] = v;
        S.stE[t] = dup2(fmaxf(v, 0.f));
    }
    __syncthreads();

    // bias: 256 threads cover NT*DOUT = 256
    {
        int nt = t >> 6, o = t & 63;
        float s = 0.f;
#pragma unroll
        for (int d = 0; d < DD; d++)
            s = fmaf(S.sE[nt * DD + d], bpool[((size_t)c * DD + d) * DOUT + o], s);
        S.sbb[t] = s;
    }

    // W generation (packed): thread owns 4 consecutive floats per pg (4 pgs).
    const float* wpc = wpool + (size_t)c * DD * DIN * DOUT;
#pragma unroll
    for (int pg = 0; pg < 4; pg++) {
        u64 acc[2][NT];
#pragma unroll
        for (int h = 0; h < 2; h++)
#pragma unroll
            for (int nt = 0; nt < NT; nt++) acc[h][nt] = 0ull;
#pragma unroll
        for (int d = 0; d < DD; d++) {
            ulonglong2 wp = *(const ulonglong2*)&wpc[(size_t)d * (DIN * DOUT) + pg * 1024 + t * 4];
#pragma unroll
            for (int nt = 0; nt < NT; nt++) {
                u64 ed = dup2(S.sE[nt * DD + d]);
                f2fma(acc[0][nt], wp.x, ed);
                f2fma(acc[1][nt], wp.y, ed);
            }
        }
#pragma unroll
        for (int nt = 0; nt < NT; nt++) {
            *(float2*)&S.sW[nt * (DIN * DOUT) + pg * 1024 + t * 4]     = u2f(acc[0][nt]);
            *(float2*)&S.sW[nt * (DIN * DOUT) + pg * 1024 + t * 4 + 2] = u2f(acc[1][nt]);
        }
    }

    // ---- Z mappings: 32 i-pairs x 8 bb-pairs ----
    const int i2  = (t & 31) * 2;
    const int bbq = (t >> 5) * 2;

    // ---- GEMM mapping: 8 o-groups x 8 bb-pairs per nt ----
    const int ntg = t >> 6;
    const int tid64 = t & 63;
    const int o0  = (tid64 & 7) * 8;
    const int bb0 = (tid64 >> 3) * 2;

    // ---- Z-gen prologue (bt=0) into buf 0 ----
    {
#pragma unroll
        for (int j = 0; j < 2; j++) {
            const int b = bbq + j;
            u64 sv[DD];
            const float* se = &g_sumEH[(size_t)b * (DD * DIN) + i2];
#pragma unroll
            for (int d = 0; d < DD; d++) sv[d] = *(const u64*)(se + d * DIN);
            float2 zr[NT];
#pragma unroll
            for (int nt = 0; nt < NT; nt++) {
                int g = S.sIdx[nt];
                float m = __ldg(&mask[(size_t)b * NN + g]);
                float2 xv = __ldcs((const float2*)(x + ((size_t)b * NN + g) * DIN + i2));
                u64 z = pk2(xv.x * m, xv.y * m);
#pragma unroll
                for (int d = 0; d < DD; d++)
                    f2fma(z, S.stE[nt * DD + d], sv[d]);
                zr[nt] = u2f(z);
            }
            if (j == 0) {
#pragma unroll
                for (int nt = 0; nt < NT; nt++) {
                    S.sZ[0][(nt * DIN + i2)     * ZP + bbq] = zr[nt].x;
                    S.sZ[0][(nt * DIN + i2 + 1) * ZP + bbq] = zr[nt].y;
                }
            } else {
#pragma unroll
                for (int nt = 0; nt < NT; nt++) {
                    S.sZ[0][(nt * DIN + i2)     * ZP + bbq + 1] = zr[nt].x;
                    S.sZ[0][(nt * DIN + i2 + 1) * ZP + bbq + 1] = zr[nt].y;
                }
            }
        }
    }
    __syncthreads();

    for (int bt = 0; bt < BB / BT; bt++) {
        const int b0 = bt * BT;
        const bool more = (bt + 1 < BB / BT);

        // ---- phase A: issue j0 loads for bt+1 (held in regs across GEMM) ----
        u64 svA[DD]; float mA[NT]; float2 xA[NT];
        int bA = 0;
        if (more) {
            bA = (bt + 1) * BT + bbq;
            const float* se = &g_sumEH[(size_t)bA * (DD * DIN) + i2];
#pragma unroll
            for (int d = 0; d < DD; d++) svA[d] = *(const u64*)(se + d * DIN);
#pragma unroll
            for (int nt = 0; nt < NT; nt++) {
                int g = S.sIdx[nt];
                mA[nt] = __ldg(&mask[(size_t)bA * NN + g]);
                xA[nt] = __ldcs((const float2*)(x + ((size_t)bA * NN + g) * DIN + i2));
            }
        }

        // ---- GEMM(bt): 2bb x 8o per thread from buf[bt&1] ----
        {
            u64 acc[2][4];
            {
                ulonglong2 bv0 = *(const ulonglong2*)&S.sbb[ntg * DOUT + o0];
                ulonglong2 bv1 = *(const ulonglong2*)&S.sbb[ntg * DOUT + o0 + 4];
                acc[0][0] = bv0.x; acc[0][1] = bv0.y; acc[0][2] = bv1.x; acc[0][3] = bv1.y;
                acc[1][0] = bv0.x; acc[1][1] = bv0.y; acc[1][2] = bv1.x; acc[1][3] = bv1.y;
            }
            const float* zb = &S.sZ[bt & 1][ntg * DIN * ZP + bb0];
            const float* wb = &S.sW[ntg * (DIN * DOUT) + o0];
#pragma unroll 8
            for (int k = 0; k < DIN; k++) {
                float2 zv = *(const float2*)(zb + k * ZP);
                ulonglong2 w0 = *(const ulonglong2*)(wb + (size_t)k * DOUT);
                ulonglong2 w1 = *(const ulonglong2*)(wb + (size_t)k * DOUT + 4);
                u64 z0 = dup2(zv.x), z1 = dup2(zv.y);
                f2fma(acc[0][0], z0, w0.x); f2fma(acc[0][1], z0, w0.y);
                f2fma(acc[0][2], z0, w1.x); f2fma(acc[0][3], z0, w1.y);
                f2fma(acc[1][0], z1, w0.x); f2fma(acc[1][1], z1, w0.y);
                f2fma(acc[1][2], z1, w1.x); f2fma(acc[1][3], z1, w1.y);
            }
#pragma unroll
            for (int j = 0; j < 2; j++) {
                int b = b0 + bb0 + j;
                float* row = out + ((size_t)b * NN + node0 + ntg) * DOUT + o0;
                float2 p0 = u2f(acc[j][0]), p1 = u2f(acc[j][1]);
                float2 p2 = u2f(acc[j][2]), p3 = u2f(acc[j][3]);
                __stcs((float4*)row,       make_float4(p0.x, p0.y, p1.x, p1.y));
                __stcs((float4*)(row + 4), make_float4(p2.x, p2.y, p3.x, p3.y));
            }
        }

        // ---- phase B: finish Z(bt+1): j0 from regs, j1 fresh; store ----
        if (more) {
            float2 zj0[NT];
#pragma unroll
            for (int nt = 0; nt < NT; nt++) {
                u64 z = pk2(xA[nt].x * mA[nt], xA[nt].y * mA[nt]);
#pragma unroll
                for (int d = 0; d < DD; d++)
                    f2fma(z, S.stE[nt * DD + d], svA[d]);
                zj0[nt] = u2f(z);
            }
            const int bB = bA + 1;
            u64 svB[DD];
            {
                const float* se = &g_sumEH[(size_t)bB * (DD * DIN) + i2];
#pragma unroll
                for (int d = 0; d < DD; d++) svB[d] = *(const u64*)(se + d * DIN);
            }
            float2 zj1[NT];
#pragma unroll
            for (int nt = 0; nt < NT; nt++) {
                int g = S.sIdx[nt];
                float m = __ldg(&mask[(size_t)bB * NN + g]);
                float2 xv = __ldcs((const float2*)(x + ((size_t)bB * NN + g) * DIN + i2));
                u64 z = pk2(xv.x * m, xv.y * m);
#pragma unroll
                for (int d = 0; d < DD; d++)
                    f2fma(z, S.stE[nt * DD + d], svB[d]);
                zj1[nt] = u2f(z);
            }
            float* buf = S.sZ[(bt + 1) & 1];
#pragma unroll
            for (int nt = 0; nt < NT; nt++) {
                *(float2*)&buf[(nt * DIN + i2)     * ZP + bbq] = make_float2(zj0[nt].x, zj1[nt].x);
                *(float2*)&buf[(nt * DIN + i2 + 1) * ZP + bbq] = make_float2(zj0[nt].y, zj1[nt].y);
            }
        }
        __syncthreads();
    }
}

// ---------------------------------------------------------------------------
extern "C" void kernel_launch(void* const* d_in, const int* in_sizes, int n_in,
                              void* d_out, int out_size)
{
    const float* x     = (const float*)d_in[0];
    const float* emb   = (const float*)d_in[1];
    const float* mask  = (const float*)d_in[3];
    const float* wpool = (const float*)d_in[4];
    const float* bpool = (const float*)d_in[5];
    const int*   nodes = (const int*)d_in[6];
    float* out = (float*)d_out;

    cudaFuncSetAttribute(k3_main, cudaFuncAttributeMaxDynamicSharedMemorySize,
                         (int)sizeof(Smem3));

    dim3 g1(K1_CHUNKS, BB);
    k1_partial<<<g1, 256>>>(x, emb, mask, nodes);

    int tot = BB * DD * DIN;
    k2_reduce<<<(tot + 255) / 256, 256>>>();

    k3_main<<<NN / NT, 256, sizeof(Smem3)>>>(x, emb, mask, wpool, bpool, nodes, out);
}

// round 15
// speedup vs baseline: 1.4376x; 1.3545x over previous
#include <cuda_runtime.h>

// Problem constants
#define BB   64
#define NN   8192
#define DIN  64
#define DOUT 64
#define DD   10
#define CC   4
#define NPC  2048

#define K1_CHUNKS 64
#define K1_NODES  (NN / K1_CHUNKS)   // 128

#define NT 4    // nodes per block in k3
#define BT 32   // batch tile (2 iterations)
#define ZPAD 36 // padded bb-row stride for sZ (floats)

typedef unsigned long long u64;

__device__ __forceinline__ u64 pk2(float lo, float hi) {
    u64 r; asm("mov.b64 %0,{%1,%2};" : "=l"(r) : "f"(lo), "f"(hi)); return r;
}
__device__ __forceinline__ u64 dup2(float v) { return pk2(v, v); }
__device__ __forceinline__ void f2fma(u64& d, u64 a, u64 b) {
    asm("fma.rn.f32x2 %0,%1,%2,%3;" : "=l"(d) : "l"(a), "l"(b), "l"(d));
}
__device__ __forceinline__ u64 f2mul(u64 a, u64 b) {
    u64 r; asm("mul.rn.f32x2 %0,%1,%2;" : "=l"(r) : "l"(a), "l"(b)); return r;
}
__device__ __forceinline__ float2 u2f(u64 v) {
    float2 f; asm("mov.b64 {%0,%1},%2;" : "=f"(f.x), "=f"(f.y) : "l"(v)); return f;
}

// Scratch
__device__ float g_part[BB * K1_CHUNKS * DD * DIN];
__device__ float g_sumEH[BB * DD * DIN];

// ---------------------------------------------------------------------------
// Kernel 1: partial sum_EH (best measured form ~46us). x streamed (__ldcs).
// ---------------------------------------------------------------------------
__global__ __launch_bounds__(256, 4) void k1_partial(
    const float* __restrict__ x, const float* __restrict__ emb,
    const float* __restrict__ mask, const int* __restrict__ nodes_per)
{
    __shared__ u64   s_tE[K1_NODES * DD];
    __shared__ int   s_g[K1_NODES];
    __shared__ float s_red[8][DD * DIN];

    const int t = threadIdx.x;
    const int b = blockIdx.y, chunk = blockIdx.x;
    const int p0 = chunk * K1_NODES;

    if (t < K1_NODES) s_g[t] = nodes_per[p0 + t];
    __syncthreads();
    for (int e = t; e < K1_NODES * DD; e += 256) {
        int p = e / DD, d = e - p * DD;
        s_tE[e] = dup2(fmaxf(emb[(size_t)s_g[p] * DD + d], 0.f));
    }
    __syncthreads();

    const int w = t >> 5, lane = t & 31;
    u64 acc[DD];
#pragma unroll
    for (int d = 0; d < DD; d++) acc[d] = 0ull;

    const float* xb = x + (size_t)b * NN * DIN + lane * 2;
    const float* mb = mask + (size_t)b * NN;
    const int base = w * (K1_NODES / 8);   // 16 nodes per warp

#pragma unroll 1
    for (int j = 0; j < K1_NODES / 8; j += 4) {
        int g4[4]; float m4[4]; float2 x4[4];
#pragma unroll
        for (int q = 0; q < 4; q++) g4[q] = s_g[base + j + q];
#pragma unroll
        for (int q = 0; q < 4; q++) {
            m4[q] = __ldg(&mb[g4[q]]);
            x4[q] = __ldcs((const float2*)(xb + (size_t)g4[q] * DIN));
        }
#pragma unroll
        for (int q = 0; q < 4; q++) {
            u64 z = f2mul(pk2(x4[q].x, x4[q].y), dup2(m4[q]));
            const u64* te = &s_tE[(base + j + q) * DD];
#pragma unroll
            for (int dp = 0; dp < DD / 2; dp++) {
                ulonglong2 tv = *(const ulonglong2*)(te + dp * 2);
                f2fma(acc[dp * 2],     tv.x, z);
                f2fma(acc[dp * 2 + 1], tv.y, z);
            }
        }
    }
#pragma unroll
    for (int d = 0; d < DD; d++)
        *(float2*)&s_red[w][d * DIN + lane * 2] = u2f(acc[d]);
    __syncthreads();
    for (int di = t; di < DD * DIN; di += 256) {
        float s = 0.f;
#pragma unroll
        for (int w2 = 0; w2 < 8; w2++) s += s_red[w2][di];
        g_part[((size_t)b * K1_CHUNKS + chunk) * (DD * DIN) + di] = s;
    }
}

__global__ __launch_bounds__(256) void k2_reduce()
{
    int idx = blockIdx.x * 256 + threadIdx.x;
    if (idx >= BB * DD * DIN) return;
    int b = idx / (DD * DIN), di = idx - b * (DD * DIN);
    float s = 0.f;
#pragma unroll
    for (int k = 0; k < K1_CHUNKS; k++)
        s += g_part[((size_t)b * K1_CHUNKS + k) * (DD * DIN) + di];
    g_sumEH[idx] = s;
}

// ---------------------------------------------------------------------------
// Kernel 3: EXACT R9 structure (best measured). 256 thr, NT=4, BT=32,
// scalar Z in [nt][k][bb] (ZPAD 36), sumEH via L1, 2 CTAs/SM.
// Only change: __ldcs on x (stream-once), __stcs on out (no L2 write-alloc).
// ---------------------------------------------------------------------------
struct Smem3 {
    float sW[NT * DIN * DOUT];      // 65536 B  [nt][k][o]
    float sZ[NT * DIN * ZPAD];      // 36864 B  [nt][k][bb(32) pad 36]
    u64   stE[NT * DD];
    float sE[NT * DD];
    float sbb[NT * DOUT];
    int   sIdx[NT];
};                                   // ~104 KB -> 2 CTAs/SM

__global__ __launch_bounds__(256, 2) void k3_main(
    const float* __restrict__ x, const float* __restrict__ emb,
    const float* __restrict__ mask, const float* __restrict__ wpool,
    const float* __restrict__ bpool, const int* __restrict__ nodes_per,
    float* __restrict__ out)
{
    extern __shared__ __align__(16) char smem_raw[];
    Smem3& S = *reinterpret_cast<Smem3*>(smem_raw);

    const int t = threadIdx.x;
    const int node0 = blockIdx.x * NT;
    const int c = node0 / NPC;

    if (t < NT) S.sIdx[t] = nodes_per[node0 + t];
    __syncthreads();
    if (t < NT * DD) {
        int nt = t / DD, d = t - nt * DD;
        float v = emb[(size_t)S.sIdx[nt] * DD + d];
        S.sE[t] = v;
        S.stE[t] = dup2(fmaxf(v, 0.f));
    }
    __syncthreads();

    // bias: 256 threads cover NT*DOUT = 256 exactly
    {
        int nt = t >> 6, o = t & 63;
        float s = 0.f;
#pragma unroll
        for (int d = 0; d < DD; d++)
            s = fmaf(S.sE[nt * DD + d], bpool[((size_t)c * DD + d) * DOUT + o], s);
        S.sbb[t] = s;
    }

    // W generation (packed): thread owns 4 consecutive floats per pg (4 pgs).
    const float* wpc = wpool + (size_t)c * DD * DIN * DOUT;
#pragma unroll
    for (int pg = 0; pg < 4; pg++) {
        u64 acc[2][NT];
#pragma unroll
        for (int h = 0; h < 2; h++)
#pragma unroll
            for (int nt = 0; nt < NT; nt++) acc[h][nt] = 0ull;
#pragma unroll
        for (int d = 0; d < DD; d++) {
            ulonglong2 wp = *(const ulonglong2*)&wpc[(size_t)d * (DIN * DOUT) + pg * 1024 + t * 4];
#pragma unroll
            for (int nt = 0; nt < NT; nt++) {
                u64 ed = dup2(S.sE[nt * DD + d]);
                f2fma(acc[0][nt], wp.x, ed);
                f2fma(acc[1][nt], wp.y, ed);
            }
        }
#pragma unroll
        for (int nt = 0; nt < NT; nt++) {
            *(float2*)&S.sW[nt * (DIN * DOUT) + pg * 1024 + t * 4]     = u2f(acc[0][nt]);
            *(float2*)&S.sW[nt * (DIN * DOUT) + pg * 1024 + t * 4 + 2] = u2f(acc[1][nt]);
        }
    }
    __syncthreads();

    // ---- Z-gen mapping: 32 i-pairs x 8 bb-quads ----
    const int i2  = (t & 31) * 2;
    const int bbq = (t >> 5) * 4;

    // ---- GEMM mapping: 8 o-groups x 8 bb-groups per nt ----
    const int ntg = t >> 6;
    const int tid64 = t & 63;
    const int o0  = (tid64 & 7) * 8;
    const int bb0 = (tid64 >> 3) * 4;

    for (int bt = 0; bt < BB / BT; bt++) {
        const int b0 = bt * BT;

        // ---- Z-gen: j (batch) outer so sumEH is loaded ONCE per batch ----
        float2 zres[NT][4];
#pragma unroll
        for (int j = 0; j < 4; j++) {
            const int b = b0 + bbq + j;
            u64 sv[DD];
            const float* se = &g_sumEH[(size_t)b * (DD * DIN) + i2];
#pragma unroll
            for (int d = 0; d < DD; d++) sv[d] = *(const u64*)(se + d * DIN);
            float m4[NT]; float2 xv4[NT];
#pragma unroll
            for (int nt = 0; nt < NT; nt++) {
                int g = S.sIdx[nt];
                m4[nt]  = __ldg(&mask[(size_t)b * NN + g]);
                xv4[nt] = __ldcs((const float2*)(x + ((size_t)b * NN + g) * DIN + i2));
            }
#pragma unroll
            for (int nt = 0; nt < NT; nt++) {
                u64 z = pk2(xv4[nt].x * m4[nt], xv4[nt].y * m4[nt]);
#pragma unroll
                for (int d = 0; d < DD; d++)
                    f2fma(z, S.stE[nt * DD + d], sv[d]);
                zres[nt][j] = u2f(z);
            }
        }
#pragma unroll
        for (int nt = 0; nt < NT; nt++) {
            *(float4*)&S.sZ[(nt * DIN + i2)     * ZPAD + bbq] =
                make_float4(zres[nt][0].x, zres[nt][1].x, zres[nt][2].x, zres[nt][3].x);
            *(float4*)&S.sZ[(nt * DIN + i2 + 1) * ZPAD + bbq] =
                make_float4(zres[nt][0].y, zres[nt][1].y, zres[nt][2].y, zres[nt][3].y);
        }
        __syncthreads();

        // ---- GEMM: thread tile 4bb x 8o ----
        u64 acc[4][4];
        {
            ulonglong2 bv0 = *(const ulonglong2*)&S.sbb[ntg * DOUT + o0];
            ulonglong2 bv1 = *(const ulonglong2*)&S.sbb[ntg * DOUT + o0 + 4];
#pragma unroll
            for (int j = 0; j < 4; j++) {
                acc[j][0] = bv0.x; acc[j][1] = bv0.y;
                acc[j][2] = bv1.x; acc[j][3] = bv1.y;
            }
        }
        const float* zbase = &S.sZ[ntg * DIN * ZPAD + bb0];
        const float* wbase = &S.sW[ntg * (DIN * DOUT) + o0];
#pragma unroll 8
        for (int k = 0; k < DIN; k++) {
            float4 zv = *(const float4*)(zbase + k * ZPAD);
            ulonglong2 w0 = *(const ulonglong2*)(wbase + (size_t)k * DOUT);
            ulonglong2 w1 = *(const ulonglong2*)(wbase + (size_t)k * DOUT + 4);
            u64 z0 = dup2(zv.x), z1 = dup2(zv.y), z2 = dup2(zv.z), z3 = dup2(zv.w);
            f2fma(acc[0][0], z0, w0.x); f2fma(acc[0][1], z0, w0.y);
            f2fma(acc[0][2], z0, w1.x); f2fma(acc[0][3], z0, w1.y);
            f2fma(acc[1][0], z1, w0.x); f2fma(acc[1][1], z1, w0.y);
            f2fma(acc[1][2], z1, w1.x); f2fma(acc[1][3], z1, w1.y);
            f2fma(acc[2][0], z2, w0.x); f2fma(acc[2][1], z2, w0.y);
            f2fma(acc[2][2], z2, w1.x); f2fma(acc[2][3], z2, w1.y);
            f2fma(acc[3][0], z3, w0.x); f2fma(acc[3][1], z3, w0.y);
            f2fma(acc[3][2], z3, w1.x); f2fma(acc[3][3], z3, w1.y);
        }
#pragma unroll
        for (int j = 0; j < 4; j++) {
            int b = b0 + bb0 + j;
            float* row = out + ((size_t)b * NN + node0 + ntg) * DOUT + o0;
            float2 p0 = u2f(acc[j][0]), p1 = u2f(acc[j][1]);
            float2 p2 = u2f(acc[j][2]), p3 = u2f(acc[j][3]);
            __stcs((float4*)row,       make_float4(p0.x, p0.y, p1.x, p1.y));
            __stcs((float4*)(row + 4), make_float4(p2.x, p2.y, p3.x, p3.y));
        }
        __syncthreads();
    }
}

// ---------------------------------------------------------------------------
extern "C" void kernel_launch(void* const* d_in, const int* in_sizes, int n_in,
                              void* d_out, int out_size)
{
    const float* x     = (const float*)d_in[0];
    const float* emb   = (const float*)d_in[1];
    const float* mask  = (const float*)d_in[3];
    const float* wpool = (const float*)d_in[4];
    const float* bpool = (const float*)d_in[5];
    const int*   nodes = (const int*)d_in[6];
    float* out = (float*)d_out;

    cudaFuncSetAttribute(k3_main, cudaFuncAttributeMaxDynamicSharedMemorySize,
                         (int)sizeof(Smem3));

    dim3 g1(K1_CHUNKS, BB);
    k1_partial<<<g1, 256>>>(x, emb, mask, nodes);

    int tot = BB * DD * DIN;
    k2_reduce<<<(tot + 255) / 256, 256>>>();

    k3_main<<<NN / NT, 256, sizeof(Smem3)>>>(x, emb, mask, wpool, bpool, nodes, out);
}

// round 16
// speedup vs baseline: 1.4793x; 1.0290x over previous
#include <cuda_runtime.h>

// Problem constants
#define BB   64
#define NN   8192
#define DIN  64
#define DOUT 64
#define DD   10
#define CC   4
#define NPC  2048

#define K1_CHUNKS 64
#define K1_NODES  (NN / K1_CHUNKS)   // 128

#define NT 4    // nodes per block in k3
#define BT 32   // batch tile (2 iterations)
#define ZPAD 36 // padded bb-row stride for sZ (floats)

typedef unsigned long long u64;

__device__ __forceinline__ u64 pk2(float lo, float hi) {
    u64 r; asm("mov.b64 %0,{%1,%2};" : "=l"(r) : "f"(lo), "f"(hi)); return r;
}
__device__ __forceinline__ u64 dup2(float v) { return pk2(v, v); }
__device__ __forceinline__ void f2fma(u64& d, u64 a, u64 b) {
    asm("fma.rn.f32x2 %0,%1,%2,%3;" : "=l"(d) : "l"(a), "l"(b), "l"(d));
}
__device__ __forceinline__ u64 f2mul(u64 a, u64 b) {
    u64 r; asm("mul.rn.f32x2 %0,%1,%2;" : "=l"(r) : "l"(a), "l"(b)); return r;
}
__device__ __forceinline__ float2 u2f(u64 v) {
    float2 f; asm("mov.b64 {%0,%1},%2;" : "=f"(f.x), "=f"(f.y) : "l"(v)); return f;
}

// Scratch
__device__ float g_part[BB * K1_CHUNKS * DD * DIN];
__device__ float g_sumEH[BB * DD * DIN];

// ---------------------------------------------------------------------------
// Kernel 1: partial sum_EH — best measured variant (R14, 46.3us):
// K1_CHUNKS=64, __ldcs on x, warp covers Din via 32 x float2.
// ---------------------------------------------------------------------------
__global__ __launch_bounds__(256, 4) void k1_partial(
    const float* __restrict__ x, const float* __restrict__ emb,
    const float* __restrict__ mask, const int* __restrict__ nodes_per)
{
    __shared__ u64   s_tE[K1_NODES * DD];
    __shared__ int   s_g[K1_NODES];
    __shared__ float s_red[8][DD * DIN];

    const int t = threadIdx.x;
    const int b = blockIdx.y, chunk = blockIdx.x;
    const int p0 = chunk * K1_NODES;

    if (t < K1_NODES) s_g[t] = nodes_per[p0 + t];
    __syncthreads();
    for (int e = t; e < K1_NODES * DD; e += 256) {
        int p = e / DD, d = e - p * DD;
        s_tE[e] = dup2(fmaxf(emb[(size_t)s_g[p] * DD + d], 0.f));
    }
    __syncthreads();

    const int w = t >> 5, lane = t & 31;
    u64 acc[DD];
#pragma unroll
    for (int d = 0; d < DD; d++) acc[d] = 0ull;

    const float* xb = x + (size_t)b * NN * DIN + lane * 2;
    const float* mb = mask + (size_t)b * NN;
    const int base = w * (K1_NODES / 8);   // 16 nodes per warp

#pragma unroll 1
    for (int j = 0; j < K1_NODES / 8; j += 4) {
        int g4[4]; float m4[4]; float2 x4[4];
#pragma unroll
        for (int q = 0; q < 4; q++) g4[q] = s_g[base + j + q];
#pragma unroll
        for (int q = 0; q < 4; q++) {
            m4[q] = __ldg(&mb[g4[q]]);
            x4[q] = __ldcs((const float2*)(xb + (size_t)g4[q] * DIN));
        }
#pragma unroll
        for (int q = 0; q < 4; q++) {
            u64 z = f2mul(pk2(x4[q].x, x4[q].y), dup2(m4[q]));
            const u64* te = &s_tE[(base + j + q) * DD];
#pragma unroll
            for (int dp = 0; dp < DD / 2; dp++) {
                ulonglong2 tv = *(const ulonglong2*)(te + dp * 2);
                f2fma(acc[dp * 2],     tv.x, z);
                f2fma(acc[dp * 2 + 1], tv.y, z);
            }
        }
    }
#pragma unroll
    for (int d = 0; d < DD; d++)
        *(float2*)&s_red[w][d * DIN + lane * 2] = u2f(acc[d]);
    __syncthreads();
    for (int di = t; di < DD * DIN; di += 256) {
        float s = 0.f;
#pragma unroll
        for (int w2 = 0; w2 < 8; w2++) s += s_red[w2][di];
        g_part[((size_t)b * K1_CHUNKS + chunk) * (DD * DIN) + di] = s;
    }
}

// ---------------------------------------------------------------------------
// Kernel 2: vectorized reduce (float4 per thread) -> g_sumEH
// ---------------------------------------------------------------------------
__global__ __launch_bounds__(256) void k2_reduce()
{
    int idx = blockIdx.x * 256 + threadIdx.x;          // quad index
    if (idx >= (BB * DD * DIN) / 4) return;
    int b = idx / (DD * DIN / 4), dq = idx - b * (DD * DIN / 4);
    float4 s = make_float4(0.f, 0.f, 0.f, 0.f);
    const float4* src = (const float4*)&g_part[(size_t)b * K1_CHUNKS * (DD * DIN)] + dq;
#pragma unroll
    for (int k = 0; k < K1_CHUNKS; k++) {
        float4 v = src[(size_t)k * (DD * DIN / 4)];
        s.x += v.x; s.y += v.y; s.z += v.z; s.w += v.w;
    }
    ((float4*)g_sumEH)[idx] = s;
}

// ---------------------------------------------------------------------------
// Kernel 3: EXACT R9 kernel (best measured: ~219us). 256 thr, NT=4, BT=32,
// scalar Z in [nt][k][bb] (ZPAD 36), sumEH via L1, 2 CTAs/SM. No cache hints.
// ---------------------------------------------------------------------------
struct Smem3 {
    float sW[NT * DIN * DOUT];      // 65536 B  [nt][k][o]
    float sZ[NT * DIN * ZPAD];      // 36864 B  [nt][k][bb(32) pad 36]
    u64   stE[NT * DD];
    float sE[NT * DD];
    float sbb[NT * DOUT];
    int   sIdx[NT];
};                                   // ~104 KB -> 2 CTAs/SM

__global__ __launch_bounds__(256, 2) void k3_main(
    const float* __restrict__ x, const float* __restrict__ emb,
    const float* __restrict__ mask, const float* __restrict__ wpool,
    const float* __restrict__ bpool, const int* __restrict__ nodes_per,
    float* __restrict__ out)
{
    extern __shared__ __align__(16) char smem_raw[];
    Smem3& S = *reinterpret_cast<Smem3*>(smem_raw);

    const int t = threadIdx.x;
    const int node0 = blockIdx.x * NT;
    const int c = node0 / NPC;

    if (t < NT) S.sIdx[t] = nodes_per[node0 + t];
    __syncthreads();
    if (t < NT * DD) {
        int nt = t / DD, d = t - nt * DD;
        float v = emb[(size_t)S.sIdx[nt] * DD + d];
        S.sE[t] = v;
        S.stE[t] = dup2(fmaxf(v, 0.f));
    }
    __syncthreads();

    // bias: 256 threads cover NT*DOUT = 256 exactly
    {
        int nt = t >> 6, o = t & 63;
        float s = 0.f;
#pragma unroll
        for (int d = 0; d < DD; d++)
            s = fmaf(S.sE[nt * DD + d], bpool[((size_t)c * DD + d) * DOUT + o], s);
        S.sbb[t] = s;
    }

    // W generation (packed): thread owns 4 consecutive floats per pg (4 pgs).
    const float* wpc = wpool + (size_t)c * DD * DIN * DOUT;
#pragma unroll
    for (int pg = 0; pg < 4; pg++) {
        u64 acc[2][NT];
#pragma unroll
        for (int h = 0; h < 2; h++)
#pragma unroll
            for (int nt = 0; nt < NT; nt++) acc[h][nt] = 0ull;
#pragma unroll
        for (int d = 0; d < DD; d++) {
            ulonglong2 wp = *(const ulonglong2*)&wpc[(size_t)d * (DIN * DOUT) + pg * 1024 + t * 4];
#pragma unroll
            for (int nt = 0; nt < NT; nt++) {
                u64 ed = dup2(S.sE[nt * DD + d]);
                f2fma(acc[0][nt], wp.x, ed);
                f2fma(acc[1][nt], wp.y, ed);
            }
        }
#pragma unroll
        for (int nt = 0; nt < NT; nt++) {
            *(float2*)&S.sW[nt * (DIN * DOUT) + pg * 1024 + t * 4]     = u2f(acc[0][nt]);
            *(float2*)&S.sW[nt * (DIN * DOUT) + pg * 1024 + t * 4 + 2] = u2f(acc[1][nt]);
        }
    }
    __syncthreads();

    // ---- Z-gen mapping: 32 i-pairs x 8 bb-quads ----
    const int i2  = (t & 31) * 2;
    const int bbq = (t >> 5) * 4;

    // ---- GEMM mapping: 8 o-groups x 8 bb-groups per nt ----
    const int ntg = t >> 6;
    const int tid64 = t & 63;
    const int o0  = (tid64 & 7) * 8;
    const int bb0 = (tid64 >> 3) * 4;

    for (int bt = 0; bt < BB / BT; bt++) {
        const int b0 = bt * BT;

        // ---- Z-gen: j (batch) outer so sumEH is loaded ONCE per batch ----
        float2 zres[NT][4];
#pragma unroll
        for (int j = 0; j < 4; j++) {
            const int b = b0 + bbq + j;
            u64 sv[DD];
            const float* se = &g_sumEH[(size_t)b * (DD * DIN) + i2];
#pragma unroll
            for (int d = 0; d < DD; d++) sv[d] = *(const u64*)(se + d * DIN);
            float m4[NT]; float2 xv4[NT];
#pragma unroll
            for (int nt = 0; nt < NT; nt++) {
                int g = S.sIdx[nt];
                m4[nt]  = __ldg(&mask[(size_t)b * NN + g]);
                xv4[nt] = *(const float2*)(x + ((size_t)b * NN + g) * DIN + i2);
            }
#pragma unroll
            for (int nt = 0; nt < NT; nt++) {
                u64 z = pk2(xv4[nt].x * m4[nt], xv4[nt].y * m4[nt]);
#pragma unroll
                for (int d = 0; d < DD; d++)
                    f2fma(z, S.stE[nt * DD + d], sv[d]);
                zres[nt][j] = u2f(z);
            }
        }
#pragma unroll
        for (int nt = 0; nt < NT; nt++) {
            *(float4*)&S.sZ[(nt * DIN + i2)     * ZPAD + bbq] =
                make_float4(zres[nt][0].x, zres[nt][1].x, zres[nt][2].x, zres[nt][3].x);
            *(float4*)&S.sZ[(nt * DIN + i2 + 1) * ZPAD + bbq] =
                make_float4(zres[nt][0].y, zres[nt][1].y, zres[nt][2].y, zres[nt][3].y);
        }
        __syncthreads();

        // ---- GEMM: thread tile 4bb x 8o ----
        u64 acc[4][4];
        {
            ulonglong2 bv0 = *(const ulonglong2*)&S.sbb[ntg * DOUT + o0];
            ulonglong2 bv1 = *(const ulonglong2*)&S.sbb[ntg * DOUT + o0 + 4];
#pragma unroll
            for (int j = 0; j < 4; j++) {
                acc[j][0] = bv0.x; acc[j][1] = bv0.y;
                acc[j][2] = bv1.x; acc[j][3] = bv1.y;
            }
        }
        const float* zbase = &S.sZ[ntg * DIN * ZPAD + bb0];
        const float* wbase = &S.sW[ntg * (DIN * DOUT) + o0];
#pragma unroll 8
        for (int k = 0; k < DIN; k++) {
            float4 zv = *(const float4*)(zbase + k * ZPAD);
            ulonglong2 w0 = *(const ulonglong2*)(wbase + (size_t)k * DOUT);
            ulonglong2 w1 = *(const ulonglong2*)(wbase + (size_t)k * DOUT + 4);
            u64 z0 = dup2(zv.x), z1 = dup2(zv.y), z2 = dup2(zv.z), z3 = dup2(zv.w);
            f2fma(acc[0][0], z0, w0.x); f2fma(acc[0][1], z0, w0.y);
            f2fma(acc[0][2], z0, w1.x); f2fma(acc[0][3], z0, w1.y);
            f2fma(acc[1][0], z1, w0.x); f2fma(acc[1][1], z1, w0.y);
            f2fma(acc[1][2], z1, w1.x); f2fma(acc[1][3], z1, w1.y);
            f2fma(acc[2][0], z2, w0.x); f2fma(acc[2][1], z2, w0.y);
            f2fma(acc[2][2], z2, w1.x); f2fma(acc[2][3], z2, w1.y);
            f2fma(acc[3][0], z3, w0.x); f2fma(acc[3][1], z3, w0.y);
            f2fma(acc[3][2], z3, w1.x); f2fma(acc[3][3], z3, w1.y);
        }
#pragma unroll
        for (int j = 0; j < 4; j++) {
            int b = b0 + bb0 + j;
            float* row = out + ((size_t)b * NN + node0 + ntg) * DOUT + o0;
            float2 p0 = u2f(acc[j][0]), p1 = u2f(acc[j][1]);
            float2 p2 = u2f(acc[j][2]), p3 = u2f(acc[j][3]);
            *(float4*)row       = make_float4(p0.x, p0.y, p1.x, p1.y);
            *(float4*)(row + 4) = make_float4(p2.x, p2.y, p3.x, p3.y);
        }
        __syncthreads();
    }
}

// ---------------------------------------------------------------------------
extern "C" void kernel_launch(void* const* d_in, const int* in_sizes, int n_in,
                              void* d_out, int out_size)
{
    const float* x     = (const float*)d_in[0];
    const float* emb   = (const float*)d_in[1];
    const float* mask  = (const float*)d_in[3];
    const float* wpool = (const float*)d_in[4];
    const float* bpool = (const float*)d_in[5];
    const int*   nodes = (const int*)d_in[6];
    float* out = (float*)d_out;

    cudaFuncSetAttribute(k3_main, cudaFuncAttributeMaxDynamicSharedMemorySize,
                         (int)sizeof(Smem3));

    dim3 g1(K1_CHUNKS, BB);
    k1_partial<<<g1, 256>>>(x, emb, mask, nodes);

    int quads = (BB * DD * DIN) / 4;
    k2_reduce<<<(quads + 255) / 256, 256>>>();

    k3_main<<<NN / NT, 256, sizeof(Smem3)>>>(x, emb, mask, wpool, bpool, nodes, out);
}